// round 3
// baseline (speedup 1.0000x reference)
#include <cuda_runtime.h>
#include <math.h>

// Problem constants
#define NB   16
#define NC   512
#define NL   4096
#define ND   384
#define NTOK 256
#define NROWS 4096      // NB*NTOK
#define NINNER 512
#define NFF  1536
#define NHEADS 8
#define NDH  64

// Scratch (device globals; allocation-free)
__device__ float g_h [NROWS*ND];      // residual stream
__device__ float g_y [NROWS*NFF];     // qkv / ff intermediate
__device__ float g_t1[NROWS*NINNER];  // xpT / attn out / hp
__device__ float g_t2[NROWS*ND];      // ln out / conv out
__device__ float g_wt[3*ND*ND];       // transposed conv weight

__device__ __forceinline__ float gelu_exact(float v) { return v * normcdff(v); }

// ---------------------------------------------------------------------------
// Pool: x[B,C,L] -> xpT[(b*256+n), c], mean over windows of 16
// ---------------------------------------------------------------------------
__global__ __launch_bounds__(256) void pool_kernel(const float* __restrict__ x,
                                                   float* __restrict__ xpT)
{
    int bc = blockIdx.x;            // 0..8191
    int b = bc >> 9, c = bc & 511;
    const float4* src = (const float4*)(x + (size_t)bc * NL) + threadIdx.x * 4;
    float s = 0.f;
#pragma unroll
    for (int j = 0; j < 4; j++) {
        float4 v = src[j];
        s += v.x + v.y + v.z + v.w;
    }
    xpT[((size_t)(b * NTOK + threadIdx.x)) * NC + c] = s * (1.f / 16.f);
}

// ---------------------------------------------------------------------------
// Generic SGEMM: C[M,N] = f(A[M,K] @ B + bias) (+ C if ACC)
// BT=true: B stored [N,K] row-major (transposed weights)
// ACT==1: exact GELU
// ---------------------------------------------------------------------------
template<int ACT, bool ACC, bool BT>
__global__ __launch_bounds__(256, 2) void gemm_kernel(
    const float* __restrict__ A, const float* __restrict__ Bm,
    const float* __restrict__ bias, float* __restrict__ C,
    int M, int N, int K)
{
    __shared__ float As[128][17];
    __shared__ float Bs[16][136];
    const int tid = threadIdx.x;
    const int tx = tid & 15, ty = tid >> 4;
    const int m0 = blockIdx.y << 7, n0 = blockIdx.x << 7;

    float acc[8][8];
#pragma unroll
    for (int i = 0; i < 8; i++)
#pragma unroll
        for (int j = 0; j < 8; j++) acc[i][j] = 0.f;

    for (int kt = 0; kt < K; kt += 16) {
#pragma unroll
        for (int r = 0; r < 2; r++) {
            int lin = tid + (r << 8);
            int arow = lin >> 2, acol = (lin & 3) << 2;
            const float4 v = *(const float4*)(A + (size_t)(m0 + arow) * K + kt + acol);
            As[arow][acol + 0] = v.x; As[arow][acol + 1] = v.y;
            As[arow][acol + 2] = v.z; As[arow][acol + 3] = v.w;
        }
        if (!BT) {
#pragma unroll
            for (int r = 0; r < 2; r++) {
                int lin = tid + (r << 8);
                int brow = lin >> 5, bcol = (lin & 31) << 2;
                *(float4*)&Bs[brow][bcol] =
                    *(const float4*)(Bm + (size_t)(kt + brow) * N + n0 + bcol);
            }
        } else {
#pragma unroll
            for (int r = 0; r < 2; r++) {
                int lin = tid + (r << 8);
                int nrow = lin >> 2, kcol = (lin & 3) << 2;
                const float4 v = *(const float4*)(Bm + (size_t)(n0 + nrow) * K + kt + kcol);
                Bs[kcol + 0][nrow] = v.x; Bs[kcol + 1][nrow] = v.y;
                Bs[kcol + 2][nrow] = v.z; Bs[kcol + 3][nrow] = v.w;
            }
        }
        __syncthreads();
#pragma unroll
        for (int kk = 0; kk < 16; kk++) {
            const float4 b0 = *(const float4*)&Bs[kk][tx * 8];
            const float4 b1 = *(const float4*)&Bs[kk][tx * 8 + 4];
#pragma unroll
            for (int i = 0; i < 8; i++) {
                const float a = As[ty * 8 + i][kk];
                acc[i][0] += a * b0.x; acc[i][1] += a * b0.y;
                acc[i][2] += a * b0.z; acc[i][3] += a * b0.w;
                acc[i][4] += a * b1.x; acc[i][5] += a * b1.y;
                acc[i][6] += a * b1.z; acc[i][7] += a * b1.w;
            }
        }
        __syncthreads();
    }

#pragma unroll
    for (int i = 0; i < 8; i++) {
        const int row = m0 + ty * 8 + i;
#pragma unroll
        for (int jv = 0; jv < 2; jv++) {
            const int col = n0 + tx * 8 + jv * 4;
            float4 r;
            r.x = acc[i][jv * 4 + 0]; r.y = acc[i][jv * 4 + 1];
            r.z = acc[i][jv * 4 + 2]; r.w = acc[i][jv * 4 + 3];
            if (bias) {
                r.x += bias[col + 0]; r.y += bias[col + 1];
                r.z += bias[col + 2]; r.w += bias[col + 3];
            }
            if (ACT == 1) {
                r.x = gelu_exact(r.x); r.y = gelu_exact(r.y);
                r.z = gelu_exact(r.z); r.w = gelu_exact(r.w);
            }
            float* cp = C + (size_t)row * N + col;
            if (ACC) {
                float4 c0 = *(const float4*)cp;
                r.x += c0.x; r.y += c0.y; r.z += c0.z; r.w += c0.w;
            }
            *(float4*)cp = r;
        }
    }
}

// ---------------------------------------------------------------------------
// LayerNorm over last dim (384). One block (128 threads) per row.
// ---------------------------------------------------------------------------
__global__ __launch_bounds__(128) void ln_kernel(const float* __restrict__ in,
                                                 const float* __restrict__ g,
                                                 const float* __restrict__ b,
                                                 float* __restrict__ out)
{
    const int row = blockIdx.x;
    const int t = threadIdx.x;
    const float* xr = in + (size_t)row * ND;
    float v0 = xr[t], v1 = xr[t + 128], v2 = xr[t + 256];
    float s = v0 + v1 + v2;
    float q = v0 * v0 + v1 * v1 + v2 * v2;
#pragma unroll
    for (int o = 16; o; o >>= 1) {
        s += __shfl_xor_sync(0xFFFFFFFFu, s, o);
        q += __shfl_xor_sync(0xFFFFFFFFu, q, o);
    }
    __shared__ float ss[4], sq[4];
    if ((t & 31) == 0) { ss[t >> 5] = s; sq[t >> 5] = q; }
    __syncthreads();
    s = ss[0] + ss[1] + ss[2] + ss[3];
    q = sq[0] + sq[1] + sq[2] + sq[3];
    const float mean = s * (1.f / ND);
    const float var  = q * (1.f / ND) - mean * mean;
    const float inv  = rsqrtf(var + 1e-5f);
    float* orow = out + (size_t)row * ND;
    orow[t]       = (v0 - mean) * inv * g[t]       + b[t];
    orow[t + 128] = (v1 - mean) * inv * g[t + 128] + b[t + 128];
    orow[t + 256] = (v2 - mean) * inv * g[t + 256] + b[t + 256];
}

// ---------------------------------------------------------------------------
// Linear attention per (b,h):
//   KV0 = relu(k)^T @ v  (64x64); W2 = rf @ (rf^T @ KV0); o = s*relu(q) @ W2
// ---------------------------------------------------------------------------
__device__ __forceinline__ void r1u(float (&acc)[4][4], float a0, float a1,
                                    float a2, float a3, const float4 b)
{
    acc[0][0] += a0 * b.x; acc[0][1] += a0 * b.y; acc[0][2] += a0 * b.z; acc[0][3] += a0 * b.w;
    acc[1][0] += a1 * b.x; acc[1][1] += a1 * b.y; acc[1][2] += a1 * b.z; acc[1][3] += a1 * b.w;
    acc[2][0] += a2 * b.x; acc[2][1] += a2 * b.y; acc[2][2] += a2 * b.z; acc[2][3] += a2 * b.w;
    acc[3][0] += a3 * b.x; acc[3][1] += a3 * b.y; acc[3][2] += a3 * b.z; acc[3][3] += a3 * b.w;
}

__global__ __launch_bounds__(256) void attn_kernel(const float* __restrict__ qkv,
                                                   const float* __restrict__ rf,
                                                   float* __restrict__ o)
{
    __shared__ float rf_s[4096];
    __shared__ float bufA[4096];
    __shared__ float bufB[4096];
    const int tid = threadIdx.x;
    const int bh = blockIdx.x;
    const int b = bh >> 3, h = bh & 7;
    const int tq = tid >> 4, tr = tid & 15;

#pragma unroll
    for (int j = 0; j < 4; j++)
        ((float4*)rf_s)[tid + j * 256] = ((const float4*)rf)[tid + j * 256];

    const float* base = qkv + (size_t)b * NTOK * NFF + h * NDH;

    // Phase 1: KV0[dk][d] = sum_n relu(k[n,dk]) * v[n,d]
    float kv[4][4];
#pragma unroll
    for (int i = 0; i < 4; i++)
#pragma unroll
        for (int j = 0; j < 4; j++) kv[i][j] = 0.f;

    for (int n0 = 0; n0 < NTOK; n0 += 64) {
        __syncthreads();
#pragma unroll
        for (int j = 0; j < 4; j++) {
            int lin = tid + j * 256;
            int rowi = lin >> 4, c4 = (lin & 15) << 2;
            const float* rp = base + (size_t)(n0 + rowi) * NFF;
            float4 kk = *(const float4*)(rp + NINNER + c4);
            kk.x = fmaxf(kk.x, 0.f); kk.y = fmaxf(kk.y, 0.f);
            kk.z = fmaxf(kk.z, 0.f); kk.w = fmaxf(kk.w, 0.f);
            *(float4*)&bufA[rowi * 64 + c4] = kk;
            *(float4*)&bufB[rowi * 64 + c4] = *(const float4*)(rp + 2 * NINNER + c4);
        }
        __syncthreads();
#pragma unroll 8
        for (int nn = 0; nn < 64; nn++) {
            float4 ka = *(const float4*)&bufA[nn * 64 + tq * 4];
            float4 vb = *(const float4*)&bufB[nn * 64 + tr * 4];
            r1u(kv, ka.x, ka.y, ka.z, ka.w, vb);
        }
    }
    __syncthreads();
#pragma unroll
    for (int i = 0; i < 4; i++) {
        float4 v = make_float4(kv[i][0], kv[i][1], kv[i][2], kv[i][3]);
        *(float4*)&bufA[(tq * 4 + i) * 64 + tr * 4] = v;
    }
    __syncthreads();

    // W1[m][d] = sum_dk rf[dk][m] * KV0[dk][d]
    float w1[4][4];
#pragma unroll
    for (int i = 0; i < 4; i++)
#pragma unroll
        for (int j = 0; j < 4; j++) w1[i][j] = 0.f;
#pragma unroll 8
    for (int dk = 0; dk < 64; dk++) {
        float4 rm = *(const float4*)&rf_s[dk * 64 + tq * 4];
        float4 kd = *(const float4*)&bufA[dk * 64 + tr * 4];
        r1u(w1, rm.x, rm.y, rm.z, rm.w, kd);
    }
    __syncthreads();
#pragma unroll
    for (int i = 0; i < 4; i++) {
        float4 v = make_float4(w1[i][0], w1[i][1], w1[i][2], w1[i][3]);
        *(float4*)&bufB[(tq * 4 + i) * 64 + tr * 4] = v;
    }
    __syncthreads();

    // W2[dq][d] = sum_m rf[dq][m] * W1[m][d]
    float w2[4][4];
#pragma unroll
    for (int i = 0; i < 4; i++)
#pragma unroll
        for (int j = 0; j < 4; j++) w2[i][j] = 0.f;
#pragma unroll 8
    for (int m = 0; m < 64; m++) {
        float4 wd = *(const float4*)&bufB[m * 64 + tr * 4];
        float r0 = rf_s[(tq * 4 + 0) * 64 + m];
        float r1 = rf_s[(tq * 4 + 1) * 64 + m];
        float r2 = rf_s[(tq * 4 + 2) * 64 + m];
        float r3 = rf_s[(tq * 4 + 3) * 64 + m];
        r1u(w2, r0, r1, r2, r3, wd);
    }
    __syncthreads();
#pragma unroll
    for (int i = 0; i < 4; i++) {
        float4 v = make_float4(w2[i][0], w2[i][1], w2[i][2], w2[i][3]);
        *(float4*)&bufA[(tq * 4 + i) * 64 + tr * 4] = v;
    }
    __syncthreads();

    // Phase 3: o[n][d] = sum_dq (relu(q[n,dq])*SCALE) * W2[dq][d]
    for (int n0 = 0; n0 < NTOK; n0 += 64) {
#pragma unroll
        for (int j = 0; j < 4; j++) {
            int lin = tid + j * 256;
            int rowi = lin >> 4, c4 = (lin & 15) << 2;
            const float* rp = base + (size_t)(n0 + rowi) * NFF;
            float4 qq = *(const float4*)(rp + c4);
            qq.x = fmaxf(qq.x, 0.f) * 0.125f; qq.y = fmaxf(qq.y, 0.f) * 0.125f;
            qq.z = fmaxf(qq.z, 0.f) * 0.125f; qq.w = fmaxf(qq.w, 0.f) * 0.125f;
            *(float4*)&bufB[rowi * 64 + c4] = qq;
        }
        __syncthreads();
        float oc[4][4];
#pragma unroll
        for (int i = 0; i < 4; i++)
#pragma unroll
            for (int j = 0; j < 4; j++) oc[i][j] = 0.f;
#pragma unroll 8
        for (int dq = 0; dq < 64; dq++) {
            float4 wd = *(const float4*)&bufA[dq * 64 + tr * 4];
            float q0 = bufB[(tq * 4 + 0) * 64 + dq];
            float q1 = bufB[(tq * 4 + 1) * 64 + dq];
            float q2 = bufB[(tq * 4 + 2) * 64 + dq];
            float q3 = bufB[(tq * 4 + 3) * 64 + dq];
            r1u(oc, q0, q1, q2, q3, wd);
        }
#pragma unroll
        for (int i = 0; i < 4; i++) {
            float4 v = make_float4(oc[i][0], oc[i][1], oc[i][2], oc[i][3]);
            *(float4*)(o + (size_t)(b * NTOK + n0 + tq * 4 + i) * NINNER + h * NDH + tr * 4) = v;
        }
        __syncthreads();
    }
}

// ---------------------------------------------------------------------------
// Conv weight transpose: local_w[dout,din,k] -> wt[k,din,dout]
// ---------------------------------------------------------------------------
__global__ __launch_bounds__(256) void wtrans_kernel(const float* __restrict__ lw,
                                                     float* __restrict__ wt)
{
    int idx = blockIdx.x * 256 + threadIdx.x;
    if (idx >= 3 * ND * ND) return;
    int k = idx / (ND * ND);
    int rem = idx - k * ND * ND;
    int din = rem / ND, dout = rem - din * ND;
    wt[idx] = lw[(dout * ND + din) * 3 + k];
}

// ---------------------------------------------------------------------------
// Local conv (k=3, pad=1 over token dim, per-batch) + residual + bias:
//   out[r,dout] = h[r,dout] + lb[dout] + sum_{k,din} wt[k,din,dout]*h[r+k-1,din]
// ---------------------------------------------------------------------------
__global__ __launch_bounds__(256) void conv_kernel(const float* __restrict__ h,
                                                   const float* __restrict__ wt,
                                                   const float* __restrict__ lb,
                                                   float* __restrict__ out)
{
    __shared__ float As[64][17];
    __shared__ float Bs[16][72];
    const int tid = threadIdx.x;
    const int tx = tid & 15, ty = tid >> 4;
    const int m0 = blockIdx.y << 6, n0 = blockIdx.x << 6;

    float acc[4][4];
#pragma unroll
    for (int i = 0; i < 4; i++)
#pragma unroll
        for (int j = 0; j < 4; j++) acc[i][j] = 0.f;

    for (int k = 0; k < 3; k++) {
        const float* Bbase = wt + (size_t)k * ND * ND;
        for (int dt = 0; dt < ND; dt += 16) {
            {
                int arow = tid >> 2, acol = (tid & 3) << 2;
                int row = m0 + arow;
                int nn = row & 255;
                int src = nn + k - 1;
                float4 v = make_float4(0.f, 0.f, 0.f, 0.f);
                if (src >= 0 && src < 256)
                    v = *(const float4*)(h + (size_t)(row + k - 1) * ND + dt + acol);
                As[arow][acol + 0] = v.x; As[arow][acol + 1] = v.y;
                As[arow][acol + 2] = v.z; As[arow][acol + 3] = v.w;
            }
            {
                int brow = tid >> 4, bcol = (tid & 15) << 2;
                *(float4*)&Bs[brow][bcol] =
                    *(const float4*)(Bbase + (size_t)(dt + brow) * ND + n0 + bcol);
            }
            __syncthreads();
#pragma unroll
            for (int kk = 0; kk < 16; kk++) {
                float4 b4 = *(const float4*)&Bs[kk][tx * 4];
#pragma unroll
                for (int i = 0; i < 4; i++) {
                    float a = As[ty * 4 + i][kk];
                    acc[i][0] += a * b4.x; acc[i][1] += a * b4.y;
                    acc[i][2] += a * b4.z; acc[i][3] += a * b4.w;
                }
            }
            __syncthreads();
        }
    }
#pragma unroll
    for (int i = 0; i < 4; i++) {
        int row = m0 + ty * 4 + i;
        int col = n0 + tx * 4;
        float4 hv = *(const float4*)(h + (size_t)row * ND + col);
        float4 r;
        r.x = hv.x + acc[i][0] + lb[col + 0];
        r.y = hv.y + acc[i][1] + lb[col + 1];
        r.z = hv.z + acc[i][2] + lb[col + 2];
        r.w = hv.w + acc[i][3] + lb[col + 3];
        *(float4*)(out + (size_t)row * ND + col) = r;
    }
}

// ---------------------------------------------------------------------------
// Final: out[b,c,l] = interp(hp)[b,c,l] + x[b,c,l]  (hp includes proj_out bias)
// ---------------------------------------------------------------------------
__global__ __launch_bounds__(256) void final_kernel(const float* __restrict__ hp,
                                                    const float* __restrict__ x,
                                                    float* __restrict__ out)
{
    size_t idx = (size_t)blockIdx.x * 256 + threadIdx.x;
    int l = (int)(idx & 4095);
    int c = (int)((idx >> 12) & 511);
    int b = (int)(idx >> 21);
    float src = fmaxf((l + 0.5f) * 0.0625f - 0.5f, 0.f);
    int i0 = (int)src;               // src >= 0 so truncation == floor
    float w = src - (float)i0;
    int i1 = min(i0 + 1, 255);
    float v0 = hp[(size_t)(b * NTOK + i0) * NC + c];
    float v1 = hp[(size_t)(b * NTOK + i1) * NC + c];
    out[idx] = v0 * (1.f - w) + v1 * w + x[idx];
}

// ---------------------------------------------------------------------------
// Host orchestration
// ---------------------------------------------------------------------------
extern "C" void kernel_launch(void* const* d_in, const int* in_sizes, int n_in,
                              void* d_out, int out_size)
{
    const float* x          = (const float*)d_in[0];
    const float* proj_in_w  = (const float*)d_in[1];
    const float* proj_in_b  = (const float*)d_in[2];
    const float* norm_in_g  = (const float*)d_in[3];
    const float* norm_in_b  = (const float*)d_in[4];
    const float* ln1_g      = (const float*)d_in[5];
    const float* ln1_b      = (const float*)d_in[6];
    const float* wqkv       = (const float*)d_in[7];
    const float* rf         = (const float*)d_in[8];
    const float* wout       = (const float*)d_in[9];
    const float* bout       = (const float*)d_in[10];
    const float* ln2_g      = (const float*)d_in[11];
    const float* ln2_b      = (const float*)d_in[12];
    const float* ffw1       = (const float*)d_in[13];
    const float* ffb1       = (const float*)d_in[14];
    const float* ffw2       = (const float*)d_in[15];
    const float* ffb2       = (const float*)d_in[16];
    const float* local_w    = (const float*)d_in[17];
    const float* local_b    = (const float*)d_in[18];
    const float* norm_out_g = (const float*)d_in[19];
    const float* norm_out_b = (const float*)d_in[20];
    const float* proj_out_w = (const float*)d_in[21];
    const float* proj_out_b = (const float*)d_in[22];
    float* out = (float*)d_out;

    float *h_, *y_, *t1_, *t2_, *wt_;
    cudaGetSymbolAddress((void**)&h_,  g_h);
    cudaGetSymbolAddress((void**)&y_,  g_y);
    cudaGetSymbolAddress((void**)&t1_, g_t1);
    cudaGetSymbolAddress((void**)&t2_, g_t2);
    cudaGetSymbolAddress((void**)&wt_, g_wt);

    // 1. pool -> xpT (t1)
    pool_kernel<<<NB * NC, 256>>>(x, t1_);
    // 2. h = xpT @ proj_in_w^T + b   (M=4096, N=384, K=512, BT)
    gemm_kernel<0, false, true><<<dim3(3, 32), 256>>>(t1_, proj_in_w, proj_in_b, h_,
                                                      NROWS, ND, NC);
    // 3. norm_in (in-place)
    ln_kernel<<<NROWS, 128>>>(h_, norm_in_g, norm_in_b, h_);

    for (int i = 0; i < 2; i++) {
        ln_kernel<<<NROWS, 128>>>(h_, ln1_g + i * ND, ln1_b + i * ND, t2_);
        gemm_kernel<0, false, false><<<dim3(12, 32), 256>>>(t2_, wqkv + (size_t)i * ND * NFF,
                                                            nullptr, y_, NROWS, NFF, ND);
        attn_kernel<<<NB * NHEADS, 256>>>(y_, rf + i * NDH * NDH, t1_);
        gemm_kernel<0, true, false><<<dim3(3, 32), 256>>>(t1_, wout + (size_t)i * NINNER * ND,
                                                          bout + i * ND, h_, NROWS, ND, NINNER);
        ln_kernel<<<NROWS, 128>>>(h_, ln2_g + i * ND, ln2_b + i * ND, t2_);
        gemm_kernel<1, false, false><<<dim3(12, 32), 256>>>(t2_, ffw1 + (size_t)i * ND * NFF,
                                                            ffb1 + i * NFF, y_, NROWS, NFF, ND);
        gemm_kernel<0, true, false><<<dim3(3, 32), 256>>>(y_, ffw2 + (size_t)i * NFF * ND,
                                                          ffb2 + i * ND, h_, NROWS, ND, NFF);
    }

    // local conv + residual
    wtrans_kernel<<<(3 * ND * ND + 255) / 256, 256>>>(local_w, wt_);
    conv_kernel<<<dim3(6, 64), 256>>>(h_, wt_, local_b, t2_);
    // norm_out
    ln_kernel<<<NROWS, 128>>>(t2_, norm_out_g, norm_out_b, h_);
    // hp = h @ proj_out_w^T + proj_out_b   (M=4096, N=512, K=384, BT)
    gemm_kernel<0, false, true><<<dim3(4, 32), 256>>>(h_, proj_out_w, proj_out_b, t1_,
                                                      NROWS, NC, ND);
    // interp + residual with x
    final_kernel<<<(NB * NC * NL) / 256, 256>>>(t1_, x, out);
}

// round 4
// speedup vs baseline: 2.0392x; 2.0392x over previous
#include <cuda_runtime.h>
#include <math.h>

// Problem constants
#define NB   16
#define NC   512
#define NL   4096
#define ND   384
#define NTOK 256
#define NROWS 4096      // NB*NTOK
#define NINNER 512
#define NFF  1536
#define NHEADS 8
#define NDH  64

// Scratch (device globals; allocation-free)
__device__ float g_h [NROWS*ND];      // residual stream
__device__ float g_y [NROWS*NFF];     // qkv / ff intermediate / conv gather
__device__ float g_t1[NROWS*NINNER];  // xpT / attn out / hp
__device__ float g_t2[NROWS*ND];      // ln out / conv out
__device__ float g_wt[3*ND*ND];       // conv weight as [k*384+din][dout]
__device__ float g_wA[NC*ND];         // proj_in_w transposed  [512][384]
__device__ float g_wB[ND*NC];         // proj_out_w transposed [384][512]

__device__ __forceinline__ float gelu_exact(float v) { return v * normcdff(v); }

__device__ __forceinline__ unsigned f2tf(float f) {
    unsigned u; asm("cvt.rna.tf32.f32 %0, %1;" : "=r"(u) : "f"(f)); return u;
}

__device__ __forceinline__ void mma_tf32(float (&d)[4], const unsigned (&a)[4],
                                         const unsigned (&b)[2]) {
    asm volatile(
        "mma.sync.aligned.m16n8k8.row.col.f32.tf32.tf32.f32 "
        "{%0,%1,%2,%3}, {%4,%5,%6,%7}, {%8,%9}, {%0,%1,%2,%3};\n"
        : "+f"(d[0]), "+f"(d[1]), "+f"(d[2]), "+f"(d[3])
        : "r"(a[0]), "r"(a[1]), "r"(a[2]), "r"(a[3]), "r"(b[0]), "r"(b[1]));
}

// ---------------------------------------------------------------------------
// Pool: x[B,C,L] -> xpT[(b*256+n), c], mean over windows of 16
// ---------------------------------------------------------------------------
__global__ __launch_bounds__(256) void pool_kernel(const float* __restrict__ x,
                                                   float* __restrict__ xpT)
{
    int bc = blockIdx.x;            // 0..8191
    int b = bc >> 9, c = bc & 511;
    const float4* src = (const float4*)(x + (size_t)bc * NL) + threadIdx.x * 4;
    float s = 0.f;
#pragma unroll
    for (int j = 0; j < 4; j++) {
        float4 v = src[j];
        s += v.x + v.y + v.z + v.w;
    }
    xpT[((size_t)(b * NTOK + threadIdx.x)) * NC + c] = s * (1.f / 16.f);
}

// ---------------------------------------------------------------------------
// TF32 tensor-core GEMM: C[M,N] = f(A[M,K] @ B[K,N] + bias) (+ C if ACC)
// Block: BM x 128, 128 threads (4 warps, 2x2), warp tile (BM/2) x 64.
// K consumed in slices of 32 (4 mma k-steps of 8).
// ---------------------------------------------------------------------------
template<int MT, int ACT, bool ACC>
__global__ __launch_bounds__(128, 2) void tgemm(
    const float* __restrict__ A, const float* __restrict__ Bm,
    const float* __restrict__ bias, float* __restrict__ C,
    int M, int N, int K)
{
    constexpr int BM = MT * 32;
    constexpr int LA = BM / 16;          // float4 staging regs for A per thread
    __shared__ unsigned As[BM * 36];     // [m][k], padded stride 36
    __shared__ unsigned Bs[32 * 136];    // [k][n], padded stride 136

    const int tid = threadIdx.x;
    const int lane = tid & 31, wid = tid >> 5;
    const int wm = (wid >> 1) * (MT * 16);
    const int wn = (wid & 1) * 64;
    const int m0 = blockIdx.y * BM, n0 = blockIdx.x * 128;

    float acc[MT][8][4];
#pragma unroll
    for (int mt = 0; mt < MT; mt++)
#pragma unroll
        for (int nt = 0; nt < 8; nt++)
#pragma unroll
            for (int i = 0; i < 4; i++) acc[mt][nt][i] = 0.f;

    float4 stA[LA], stB[8];

    // prologue: load slice 0
#pragma unroll
    for (int i = 0; i < LA; i++) {
        int lin = tid + i * 128;
        int row = lin >> 3, c4 = (lin & 7) << 2;
        stA[i] = *(const float4*)(A + (size_t)(m0 + row) * K + c4);
    }
#pragma unroll
    for (int i = 0; i < 8; i++) {
        int lin = tid + i * 128;
        int row = lin >> 5, c4 = (lin & 31) << 2;
        stB[i] = *(const float4*)(Bm + (size_t)row * N + n0 + c4);
    }

    const int NS = K >> 5;
    for (int s = 0; s < NS; s++) {
        // commit staged slice to smem (tf32-rounded)
#pragma unroll
        for (int i = 0; i < LA; i++) {
            int lin = tid + i * 128;
            int row = lin >> 3, c4 = (lin & 7) << 2;
            uint4 p = make_uint4(f2tf(stA[i].x), f2tf(stA[i].y),
                                 f2tf(stA[i].z), f2tf(stA[i].w));
            *(uint4*)&As[row * 36 + c4] = p;
        }
#pragma unroll
        for (int i = 0; i < 8; i++) {
            int lin = tid + i * 128;
            int row = lin >> 5, c4 = (lin & 31) << 2;
            uint4 p = make_uint4(f2tf(stB[i].x), f2tf(stB[i].y),
                                 f2tf(stB[i].z), f2tf(stB[i].w));
            *(uint4*)&Bs[row * 136 + c4] = p;
        }
        __syncthreads();

        // prefetch next slice (overlaps with mma below)
        if (s + 1 < NS) {
            int ks = (s + 1) << 5;
#pragma unroll
            for (int i = 0; i < LA; i++) {
                int lin = tid + i * 128;
                int row = lin >> 3, c4 = (lin & 7) << 2;
                stA[i] = *(const float4*)(A + (size_t)(m0 + row) * K + ks + c4);
            }
#pragma unroll
            for (int i = 0; i < 8; i++) {
                int lin = tid + i * 128;
                int row = lin >> 5, c4 = (lin & 31) << 2;
                stB[i] = *(const float4*)(Bm + (size_t)(ks + row) * N + n0 + c4);
            }
        }

#pragma unroll
        for (int kk = 0; kk < 4; kk++) {
            const int kb = kk << 3;
            unsigned af[MT][4], bf[8][2];
#pragma unroll
            for (int mt = 0; mt < MT; mt++) {
                int r = wm + mt * 16 + (lane >> 2);
                int k = kb + (lane & 3);
                af[mt][0] = As[r * 36 + k];
                af[mt][1] = As[(r + 8) * 36 + k];
                af[mt][2] = As[r * 36 + k + 4];
                af[mt][3] = As[(r + 8) * 36 + k + 4];
            }
#pragma unroll
            for (int nt = 0; nt < 8; nt++) {
                int c = wn + nt * 8 + (lane >> 2);
                int k = kb + (lane & 3);
                bf[nt][0] = Bs[k * 136 + c];
                bf[nt][1] = Bs[(k + 4) * 136 + c];
            }
#pragma unroll
            for (int mt = 0; mt < MT; mt++)
#pragma unroll
                for (int nt = 0; nt < 8; nt++)
                    mma_tf32(acc[mt][nt], af[mt], bf[nt]);
        }
        __syncthreads();
    }

    // epilogue
#pragma unroll
    for (int mt = 0; mt < MT; mt++) {
#pragma unroll
        for (int nt = 0; nt < 8; nt++) {
#pragma unroll
            for (int half = 0; half < 2; half++) {
                int row = m0 + wm + mt * 16 + (lane >> 2) + half * 8;
                int col = n0 + wn + nt * 8 + (lane & 3) * 2;
                float2 r;
                r.x = acc[mt][nt][half * 2];
                r.y = acc[mt][nt][half * 2 + 1];
                if (bias) { r.x += bias[col]; r.y += bias[col + 1]; }
                if (ACT == 1) { r.x = gelu_exact(r.x); r.y = gelu_exact(r.y); }
                float* cp = C + (size_t)row * N + col;
                if (ACC) { r.x += cp[0]; r.y += cp[1]; }
                *(float2*)cp = r;
            }
        }
    }
}

// ---------------------------------------------------------------------------
// LayerNorm over last dim (384). Warp per row, 8 rows per block.
// ---------------------------------------------------------------------------
__global__ __launch_bounds__(256) void ln_kernel(const float* __restrict__ in,
                                                 const float* __restrict__ g,
                                                 const float* __restrict__ b,
                                                 float* __restrict__ out)
{
    const int wid = threadIdx.x >> 5, lane = threadIdx.x & 31;
    const int row = blockIdx.x * 8 + wid;
    const float* xr = in + (size_t)row * ND;
    float4 v0 = *(const float4*)(xr + lane * 4);
    float4 v1 = *(const float4*)(xr + 128 + lane * 4);
    float4 v2 = *(const float4*)(xr + 256 + lane * 4);
    float s = v0.x + v0.y + v0.z + v0.w + v1.x + v1.y + v1.z + v1.w
            + v2.x + v2.y + v2.z + v2.w;
    float q = v0.x*v0.x + v0.y*v0.y + v0.z*v0.z + v0.w*v0.w
            + v1.x*v1.x + v1.y*v1.y + v1.z*v1.z + v1.w*v1.w
            + v2.x*v2.x + v2.y*v2.y + v2.z*v2.z + v2.w*v2.w;
#pragma unroll
    for (int o = 16; o; o >>= 1) {
        s += __shfl_xor_sync(0xFFFFFFFFu, s, o);
        q += __shfl_xor_sync(0xFFFFFFFFu, q, o);
    }
    const float mean = s * (1.f / ND);
    const float var  = q * (1.f / ND) - mean * mean;
    const float inv  = rsqrtf(var + 1e-5f);
    float* orow = out + (size_t)row * ND;
#pragma unroll
    for (int j = 0; j < 3; j++) {
        int col = j * 128 + lane * 4;
        float4 v = (j == 0) ? v0 : (j == 1) ? v1 : v2;
        float4 gg = *(const float4*)(g + col);
        float4 bb = *(const float4*)(b + col);
        float4 r;
        r.x = (v.x - mean) * inv * gg.x + bb.x;
        r.y = (v.y - mean) * inv * gg.y + bb.y;
        r.z = (v.z - mean) * inv * gg.z + bb.z;
        r.w = (v.w - mean) * inv * gg.w + bb.w;
        *(float4*)(orow + col) = r;
    }
}

// ---------------------------------------------------------------------------
// Linear attention per (b,h) (unchanged fp32 path; ~0.6 GFLOP total)
// ---------------------------------------------------------------------------
__device__ __forceinline__ void r1u(float (&acc)[4][4], float a0, float a1,
                                    float a2, float a3, const float4 b)
{
    acc[0][0] += a0 * b.x; acc[0][1] += a0 * b.y; acc[0][2] += a0 * b.z; acc[0][3] += a0 * b.w;
    acc[1][0] += a1 * b.x; acc[1][1] += a1 * b.y; acc[1][2] += a1 * b.z; acc[1][3] += a1 * b.w;
    acc[2][0] += a2 * b.x; acc[2][1] += a2 * b.y; acc[2][2] += a2 * b.z; acc[2][3] += a2 * b.w;
    acc[3][0] += a3 * b.x; acc[3][1] += a3 * b.y; acc[3][2] += a3 * b.z; acc[3][3] += a3 * b.w;
}

__global__ __launch_bounds__(256) void attn_kernel(const float* __restrict__ qkv,
                                                   const float* __restrict__ rf,
                                                   float* __restrict__ o)
{
    __shared__ float rf_s[4096];
    __shared__ float bufA[4096];
    __shared__ float bufB[4096];
    const int tid = threadIdx.x;
    const int bh = blockIdx.x;
    const int b = bh >> 3, h = bh & 7;
    const int tq = tid >> 4, tr = tid & 15;

#pragma unroll
    for (int j = 0; j < 4; j++)
        ((float4*)rf_s)[tid + j * 256] = ((const float4*)rf)[tid + j * 256];

    const float* base = qkv + (size_t)b * NTOK * NFF + h * NDH;

    float kv[4][4];
#pragma unroll
    for (int i = 0; i < 4; i++)
#pragma unroll
        for (int j = 0; j < 4; j++) kv[i][j] = 0.f;

    for (int n0 = 0; n0 < NTOK; n0 += 64) {
        __syncthreads();
#pragma unroll
        for (int j = 0; j < 4; j++) {
            int lin = tid + j * 256;
            int rowi = lin >> 4, c4 = (lin & 15) << 2;
            const float* rp = base + (size_t)(n0 + rowi) * NFF;
            float4 kk = *(const float4*)(rp + NINNER + c4);
            kk.x = fmaxf(kk.x, 0.f); kk.y = fmaxf(kk.y, 0.f);
            kk.z = fmaxf(kk.z, 0.f); kk.w = fmaxf(kk.w, 0.f);
            *(float4*)&bufA[rowi * 64 + c4] = kk;
            *(float4*)&bufB[rowi * 64 + c4] = *(const float4*)(rp + 2 * NINNER + c4);
        }
        __syncthreads();
#pragma unroll 8
        for (int nn = 0; nn < 64; nn++) {
            float4 ka = *(const float4*)&bufA[nn * 64 + tq * 4];
            float4 vb = *(const float4*)&bufB[nn * 64 + tr * 4];
            r1u(kv, ka.x, ka.y, ka.z, ka.w, vb);
        }
    }
    __syncthreads();
#pragma unroll
    for (int i = 0; i < 4; i++) {
        float4 v = make_float4(kv[i][0], kv[i][1], kv[i][2], kv[i][3]);
        *(float4*)&bufA[(tq * 4 + i) * 64 + tr * 4] = v;
    }
    __syncthreads();

    float w1[4][4];
#pragma unroll
    for (int i = 0; i < 4; i++)
#pragma unroll
        for (int j = 0; j < 4; j++) w1[i][j] = 0.f;
#pragma unroll 8
    for (int dk = 0; dk < 64; dk++) {
        float4 rm = *(const float4*)&rf_s[dk * 64 + tq * 4];
        float4 kd = *(const float4*)&bufA[dk * 64 + tr * 4];
        r1u(w1, rm.x, rm.y, rm.z, rm.w, kd);
    }
    __syncthreads();
#pragma unroll
    for (int i = 0; i < 4; i++) {
        float4 v = make_float4(w1[i][0], w1[i][1], w1[i][2], w1[i][3]);
        *(float4*)&bufB[(tq * 4 + i) * 64 + tr * 4] = v;
    }
    __syncthreads();

    float w2[4][4];
#pragma unroll
    for (int i = 0; i < 4; i++)
#pragma unroll
        for (int j = 0; j < 4; j++) w2[i][j] = 0.f;
#pragma unroll 8
    for (int m = 0; m < 64; m++) {
        float4 wd = *(const float4*)&bufB[m * 64 + tr * 4];
        float r0 = rf_s[(tq * 4 + 0) * 64 + m];
        float r1 = rf_s[(tq * 4 + 1) * 64 + m];
        float r2 = rf_s[(tq * 4 + 2) * 64 + m];
        float r3 = rf_s[(tq * 4 + 3) * 64 + m];
        r1u(w2, r0, r1, r2, r3, wd);
    }
    __syncthreads();
#pragma unroll
    for (int i = 0; i < 4; i++) {
        float4 v = make_float4(w2[i][0], w2[i][1], w2[i][2], w2[i][3]);
        *(float4*)&bufA[(tq * 4 + i) * 64 + tr * 4] = v;
    }
    __syncthreads();

    for (int n0 = 0; n0 < NTOK; n0 += 64) {
#pragma unroll
        for (int j = 0; j < 4; j++) {
            int lin = tid + j * 256;
            int rowi = lin >> 4, c4 = (lin & 15) << 2;
            const float* rp = base + (size_t)(n0 + rowi) * NFF;
            float4 qq = *(const float4*)(rp + c4);
            qq.x = fmaxf(qq.x, 0.f) * 0.125f; qq.y = fmaxf(qq.y, 0.f) * 0.125f;
            qq.z = fmaxf(qq.z, 0.f) * 0.125f; qq.w = fmaxf(qq.w, 0.f) * 0.125f;
            *(float4*)&bufB[rowi * 64 + c4] = qq;
        }
        __syncthreads();
        float oc[4][4];
#pragma unroll
        for (int i = 0; i < 4; i++)
#pragma unroll
            for (int j = 0; j < 4; j++) oc[i][j] = 0.f;
#pragma unroll 8
        for (int dq = 0; dq < 64; dq++) {
            float4 wd = *(const float4*)&bufA[dq * 64 + tr * 4];
            float q0 = bufB[(tq * 4 + 0) * 64 + dq];
            float q1 = bufB[(tq * 4 + 1) * 64 + dq];
            float q2 = bufB[(tq * 4 + 2) * 64 + dq];
            float q3 = bufB[(tq * 4 + 3) * 64 + dq];
            r1u(oc, q0, q1, q2, q3, wd);
        }
#pragma unroll
        for (int i = 0; i < 4; i++) {
            float4 v = make_float4(oc[i][0], oc[i][1], oc[i][2], oc[i][3]);
            *(float4*)(o + (size_t)(b * NTOK + n0 + tq * 4 + i) * NINNER + h * NDH + tr * 4) = v;
        }
        __syncthreads();
    }
}

// ---------------------------------------------------------------------------
// Conv weight reshape: local_w[dout,din,k] -> wt[k*384+din][dout]
// ---------------------------------------------------------------------------
__global__ __launch_bounds__(256) void wtrans_kernel(const float* __restrict__ lw,
                                                     float* __restrict__ wt)
{
    int idx = blockIdx.x * 256 + threadIdx.x;
    if (idx >= 3 * ND * ND) return;
    int k = idx / (ND * ND);
    int rem = idx - k * ND * ND;
    int din = rem / ND, dout = rem - din * ND;
    wt[idx] = lw[(dout * ND + din) * 3 + k];
}

// proj_in_w[D=384][C=512] -> wA[c][d]
__global__ __launch_bounds__(256) void transA_kernel(const float* __restrict__ w,
                                                     float* __restrict__ wo)
{
    int idx = blockIdx.x * 256 + threadIdx.x;
    if (idx >= NC * ND) return;
    int c = idx / ND, d = idx - c * ND;
    wo[idx] = w[d * NC + c];
}

// proj_out_w[C=512][D=384] -> wB[d][c]
__global__ __launch_bounds__(256) void transB_kernel(const float* __restrict__ w,
                                                     float* __restrict__ wo)
{
    int idx = blockIdx.x * 256 + threadIdx.x;
    if (idx >= ND * NC) return;
    int d = idx / NC, c = idx - d * NC;
    wo[idx] = w[c * ND + d];
}

// ---------------------------------------------------------------------------
// Conv gather: A_ext[r][0:384]=h[r-1](or 0), [384:768]=h[r], [768:1152]=h[r+1](or 0)
// one thread per float4 (4096 * 288 float4)
// ---------------------------------------------------------------------------
__global__ __launch_bounds__(256) void gather_kernel(const float* __restrict__ h,
                                                     float* __restrict__ aext)
{
    int idx = blockIdx.x * 256 + threadIdx.x;   // float4 index
    int r = idx / 288;
    int c4 = idx - r * 288;                     // 0..287
    int seg = c4 / 96;                          // 0,1,2
    int col = (c4 - seg * 96) * 4;
    int n = r & 255;
    int src = r + seg - 1;
    float4 v = make_float4(0.f, 0.f, 0.f, 0.f);
    bool ok = (seg == 1) || (seg == 0 && n > 0) || (seg == 2 && n < 255);
    if (ok) v = *(const float4*)(h + (size_t)src * ND + col);
    *(float4*)(aext + (size_t)r * 1152 + c4 * 4) = v;
}

// ---------------------------------------------------------------------------
// Final: out[b,c,l] = interp(hp)[b,c,l] + x[b,c,l]  (hp includes proj_out bias)
// ---------------------------------------------------------------------------
__global__ __launch_bounds__(256) void final_kernel(const float* __restrict__ hp,
                                                    const float* __restrict__ x,
                                                    float* __restrict__ out)
{
    size_t idx = (size_t)blockIdx.x * 256 + threadIdx.x;
    int l = (int)(idx & 4095);
    int c = (int)((idx >> 12) & 511);
    int b = (int)(idx >> 21);
    float src = fmaxf((l + 0.5f) * 0.0625f - 0.5f, 0.f);
    int i0 = (int)src;
    float w = src - (float)i0;
    int i1 = min(i0 + 1, 255);
    float v0 = hp[(size_t)(b * NTOK + i0) * NC + c];
    float v1 = hp[(size_t)(b * NTOK + i1) * NC + c];
    out[idx] = v0 * (1.f - w) + v1 * w + x[idx];
}

// ---------------------------------------------------------------------------
// Host orchestration
// ---------------------------------------------------------------------------
extern "C" void kernel_launch(void* const* d_in, const int* in_sizes, int n_in,
                              void* d_out, int out_size)
{
    const float* x          = (const float*)d_in[0];
    const float* proj_in_w  = (const float*)d_in[1];
    const float* proj_in_b  = (const float*)d_in[2];
    const float* norm_in_g  = (const float*)d_in[3];
    const float* norm_in_b  = (const float*)d_in[4];
    const float* ln1_g      = (const float*)d_in[5];
    const float* ln1_b      = (const float*)d_in[6];
    const float* wqkv       = (const float*)d_in[7];
    const float* rf         = (const float*)d_in[8];
    const float* wout       = (const float*)d_in[9];
    const float* bout       = (const float*)d_in[10];
    const float* ln2_g      = (const float*)d_in[11];
    const float* ln2_b      = (const float*)d_in[12];
    const float* ffw1       = (const float*)d_in[13];
    const float* ffb1       = (const float*)d_in[14];
    const float* ffw2       = (const float*)d_in[15];
    const float* ffb2       = (const float*)d_in[16];
    const float* local_w    = (const float*)d_in[17];
    const float* local_b    = (const float*)d_in[18];
    const float* norm_out_g = (const float*)d_in[19];
    const float* norm_out_b = (const float*)d_in[20];
    const float* proj_out_w = (const float*)d_in[21];
    const float* proj_out_b = (const float*)d_in[22];
    float* out = (float*)d_out;

    float *h_, *y_, *t1_, *t2_, *wt_, *wA_, *wB_;
    cudaGetSymbolAddress((void**)&h_,  g_h);
    cudaGetSymbolAddress((void**)&y_,  g_y);
    cudaGetSymbolAddress((void**)&t1_, g_t1);
    cudaGetSymbolAddress((void**)&t2_, g_t2);
    cudaGetSymbolAddress((void**)&wt_, g_wt);
    cudaGetSymbolAddress((void**)&wA_, g_wA);
    cudaGetSymbolAddress((void**)&wB_, g_wB);

    // small weight prep (independent of main chain)
    transA_kernel<<<(NC * ND + 255) / 256, 256>>>(proj_in_w, wA_);
    transB_kernel<<<(ND * NC + 255) / 256, 256>>>(proj_out_w, wB_);
    wtrans_kernel<<<(3 * ND * ND + 255) / 256, 256>>>(local_w, wt_);

    // 1. pool -> xpT (t1)
    pool_kernel<<<NB * NC, 256>>>(x, t1_);
    // 2. h = xpT @ wA + proj_in_b   (M=4096, N=384, K=512)
    tgemm<2, 0, false><<<dim3(3, 64), 128>>>(t1_, wA_, proj_in_b, h_, NROWS, ND, NC);
    // 3. norm_in (in-place)
    ln_kernel<<<NROWS / 8, 256>>>(h_, norm_in_g, norm_in_b, h_);

    for (int i = 0; i < 2; i++) {
        ln_kernel<<<NROWS / 8, 256>>>(h_, ln1_g + i * ND, ln1_b + i * ND, t2_);
        tgemm<4, 0, false><<<dim3(12, 32), 128>>>(t2_, wqkv + (size_t)i * ND * NFF,
                                                  nullptr, y_, NROWS, NFF, ND);
        attn_kernel<<<NB * NHEADS, 256>>>(y_, rf + i * NDH * NDH, t1_);
        tgemm<2, 0, true><<<dim3(3, 64), 128>>>(t1_, wout + (size_t)i * NINNER * ND,
                                                bout + i * ND, h_, NROWS, ND, NINNER);
        ln_kernel<<<NROWS / 8, 256>>>(h_, ln2_g + i * ND, ln2_b + i * ND, t2_);
        tgemm<4, 1, false><<<dim3(12, 32), 128>>>(t2_, ffw1 + (size_t)i * ND * NFF,
                                                  ffb1 + i * NFF, y_, NROWS, NFF, ND);
        tgemm<2, 0, true><<<dim3(3, 64), 128>>>(y_, ffw2 + (size_t)i * NFF * ND,
                                                ffb2 + i * ND, h_, NROWS, ND, NFF);
    }

    // local conv as one GEMM: t2 = h; t2 += gather(h) @ wt + local_b
    cudaMemcpyAsync(t2_, h_, (size_t)NROWS * ND * sizeof(float),
                    cudaMemcpyDeviceToDevice);
    gather_kernel<<<(NROWS * 288) / 256, 256>>>(h_, y_);
    tgemm<2, 0, true><<<dim3(3, 64), 128>>>(y_, wt_, local_b, t2_, NROWS, ND, 3 * ND);
    // norm_out
    ln_kernel<<<NROWS / 8, 256>>>(t2_, norm_out_g, norm_out_b, h_);
    // hp = h @ wB + proj_out_b   (M=4096, N=512, K=384)
    tgemm<2, 0, false><<<dim3(4, 64), 128>>>(h_, wB_, proj_out_b, t1_, NROWS, NC, ND);
    // interp + residual with x
    final_kernel<<<(NB * NC * NL) / 256, 256>>>(t1_, x, out);
}